// round 1
// baseline (speedup 1.0000x reference)
#include <cuda_runtime.h>
#include <cstdint>

// Problem constants
#define BATCH 2
#define SEQ   4096
#define DMODEL 512
#define NHEAD 8
#define HDIM  64

// Scratch (allocation-free rule: __device__ globals)
__device__ float g_q[BATCH * NHEAD * SEQ * HDIM];
__device__ float g_k[BATCH * NHEAD * SEQ * HDIM];
__device__ float g_v[BATCH * NHEAD * SEQ * HDIM];
__device__ float g_attn[BATCH * SEQ * DMODEL];

// ---------------------------------------------------------------------------
// NT GEMM: C[m,e] = sum_d A[m,d] * B[e,d] (+ bias[e])
// mode 0: C row-major [M,N]
// mode 1: scatter to [B, H, S, DH] layout (e = h*HDIM + dh, m = b*SEQ + s)
// ---------------------------------------------------------------------------
#define GT  64
#define GBK 16

__global__ __launch_bounds__(256)
void gemm_nt_kernel(const float* __restrict__ A, const float* __restrict__ Bm,
                    const float* __restrict__ bias, float* __restrict__ C,
                    int M, int N, int K, int mode)
{
    __shared__ float As[GBK][GT];
    __shared__ float Bs[GBK][GT];

    const int bm = blockIdx.x * GT;
    const int bn = blockIdx.y * GT;
    const int tid = threadIdx.x;
    const int tx = tid & 15;
    const int ty = tid >> 4;
    const int lr = tid >> 2;        // 0..63 row within tile
    const int lc = (tid & 3) * 4;   // 0..12 k-col start

    float c[4][4] = {};

    for (int k0 = 0; k0 < K; k0 += GBK) {
        float4 av = *(const float4*)(A  + (size_t)(bm + lr) * K + k0 + lc);
        float4 bv = *(const float4*)(Bm + (size_t)(bn + lr) * K + k0 + lc);
        As[lc + 0][lr] = av.x; As[lc + 1][lr] = av.y;
        As[lc + 2][lr] = av.z; As[lc + 3][lr] = av.w;
        Bs[lc + 0][lr] = bv.x; Bs[lc + 1][lr] = bv.y;
        Bs[lc + 2][lr] = bv.z; Bs[lc + 3][lr] = bv.w;
        __syncthreads();

        #pragma unroll
        for (int k = 0; k < GBK; k++) {
            float4 a = *(const float4*)&As[k][ty * 4];
            float4 b = *(const float4*)&Bs[k][tx * 4];
            float ar[4] = {a.x, a.y, a.z, a.w};
            float br[4] = {b.x, b.y, b.z, b.w};
            #pragma unroll
            for (int i = 0; i < 4; i++)
                #pragma unroll
                for (int j = 0; j < 4; j++)
                    c[i][j] += ar[i] * br[j];
        }
        __syncthreads();
    }

    #pragma unroll
    for (int i = 0; i < 4; i++) {
        const int m = bm + ty * 4 + i;
        #pragma unroll
        for (int j = 0; j < 4; j++) {
            const int e = bn + tx * 4 + j;
            float v = c[i][j];
            if (bias) v += bias[e];
            if (mode == 0) {
                C[(size_t)m * N + e] = v;
            } else {
                const int bb = m / SEQ, ss = m % SEQ;
                const int hh = e >> 6,  dd = e & 63;
                C[(((size_t)bb * NHEAD + hh) * SEQ + ss) * HDIM + dd] = v;
            }
        }
    }
}

// ---------------------------------------------------------------------------
// Flash attention (fp32, causal). One query row per thread, 128 rows/block.
// K/V tiles of 16 keys staged in shared; online softmax.
// Q/K/V layout: [B, H, S, DH]; output to [B, S, H*DH].
// ---------------------------------------------------------------------------
#define ABM 128
#define ABN 16

__global__ __launch_bounds__(128)
void attn_kernel(const float* __restrict__ Q, const float* __restrict__ Km,
                 const float* __restrict__ V, float* __restrict__ O)
{
    __shared__ float Ks[ABN][HDIM];
    __shared__ float Vs[ABN][HDIM];

    const int bh = blockIdx.y;                  // b*NHEAD + h
    const int NT = SEQ / ABM;                   // 32 q-tiles
    const int xt = blockIdx.x;
    // interleave heavy (late) and light (early) q-tiles for load balance
    const int qtile = (xt & 1) ? (NT - 1 - (xt >> 1)) : (xt >> 1);
    const int qb = qtile * ABM;
    const int i = threadIdx.x;
    const int qg = qb + i;

    const float* Qb = Q + (size_t)bh * SEQ * HDIM;
    const float* Kb = Km + (size_t)bh * SEQ * HDIM;
    const float* Vb = V + (size_t)bh * SEQ * HDIM;

    float q[HDIM];
    {
        const float4* qr = (const float4*)(Qb + (size_t)qg * HDIM);
        #pragma unroll
        for (int d = 0; d < HDIM / 4; d++) {
            float4 t = qr[d];
            q[4 * d + 0] = t.x; q[4 * d + 1] = t.y;
            q[4 * d + 2] = t.z; q[4 * d + 3] = t.w;
        }
    }

    float acc[HDIM];
    #pragma unroll
    for (int d = 0; d < HDIM; d++) acc[d] = 0.f;
    float mi = -1e30f, li = 0.f;

    const int lr = i >> 3;          // 0..15 key row to load
    const int lc = (i & 7) * 8;     // 8 floats per thread
    const int ntiles = (qb + ABM) / ABN;

    for (int kt = 0; kt < ntiles; kt++) {
        const float* kp = Kb + ((size_t)(kt * ABN + lr)) * HDIM + lc;
        const float* vp = Vb + ((size_t)(kt * ABN + lr)) * HDIM + lc;
        float4 k0v = ((const float4*)kp)[0];
        float4 k1v = ((const float4*)kp)[1];
        float4 v0v = ((const float4*)vp)[0];
        float4 v1v = ((const float4*)vp)[1];
        *(float4*)&Ks[lr][lc]     = k0v;
        *(float4*)&Ks[lr][lc + 4] = k1v;
        *(float4*)&Vs[lr][lc]     = v0v;
        *(float4*)&Vs[lr][lc + 4] = v1v;
        __syncthreads();

        float sc[ABN];
        float tm = -1e30f;
        const int kg0 = kt * ABN;
        #pragma unroll
        for (int j = 0; j < ABN; j++) {
            float s = 0.f;
            const float4* kk = (const float4*)&Ks[j][0];
            #pragma unroll
            for (int d = 0; d < HDIM / 4; d++) {
                float4 t = kk[d];
                s += q[4 * d + 0] * t.x + q[4 * d + 1] * t.y
                   + q[4 * d + 2] * t.z + q[4 * d + 3] * t.w;
            }
            s *= 0.125f;                        // 1/sqrt(HDIM)
            if (kg0 + j > qg) s = -1e30f;       // causal mask
            sc[j] = s;
            tm = fmaxf(tm, s);
        }

        const float newm = fmaxf(mi, tm);
        const float scale = __expf(mi - newm);
        li *= scale;
        #pragma unroll
        for (int d = 0; d < HDIM; d++) acc[d] *= scale;

        #pragma unroll
        for (int j = 0; j < ABN; j++) {
            const float p = __expf(sc[j] - newm);
            li += p;
            const float4* vv = (const float4*)&Vs[j][0];
            #pragma unroll
            for (int d = 0; d < HDIM / 4; d++) {
                float4 t = vv[d];
                acc[4 * d + 0] += p * t.x;
                acc[4 * d + 1] += p * t.y;
                acc[4 * d + 2] += p * t.z;
                acc[4 * d + 3] += p * t.w;
            }
        }
        mi = newm;
        __syncthreads();
    }

    const float inv = 1.f / li;
    const int b = bh >> 3, h = bh & 7;
    float* orow = O + (((size_t)b * SEQ + qg) * NHEAD + h) * HDIM;
    #pragma unroll
    for (int d = 0; d < HDIM / 4; d++) {
        float4 t;
        t.x = acc[4 * d + 0] * inv; t.y = acc[4 * d + 1] * inv;
        t.z = acc[4 * d + 2] * inv; t.w = acc[4 * d + 3] * inv;
        ((float4*)orow)[d] = t;
    }
}

// ---------------------------------------------------------------------------
extern "C" void kernel_launch(void* const* d_in, const int* in_sizes, int n_in,
                              void* d_out, int out_size)
{
    const float* x  = (const float*)d_in[0];
    const float* Wq = (const float*)d_in[1];
    const float* Wk = (const float*)d_in[2];
    const float* Wv = (const float*)d_in[3];
    const float* Wp = (const float*)d_in[4];
    const float* bp = (const float*)d_in[5];
    float* out = (float*)d_out;

    float *qp, *kp, *vp, *ap;
    cudaGetSymbolAddress((void**)&qp, g_q);
    cudaGetSymbolAddress((void**)&kp, g_k);
    cudaGetSymbolAddress((void**)&vp, g_v);
    cudaGetSymbolAddress((void**)&ap, g_attn);

    const int M = BATCH * SEQ;      // 8192
    const int N = DMODEL;           // 512
    const int K = DMODEL;           // 512

    dim3 gg(M / GT, N / GT);        // (128, 8)
    gemm_nt_kernel<<<gg, 256>>>(x, Wq, nullptr, qp, M, N, K, 1);
    gemm_nt_kernel<<<gg, 256>>>(x, Wk, nullptr, kp, M, N, K, 1);
    gemm_nt_kernel<<<gg, 256>>>(x, Wv, nullptr, vp, M, N, K, 1);

    dim3 ga(SEQ / ABM, BATCH * NHEAD);  // (32, 16)
    attn_kernel<<<ga, 128>>>(qp, kp, vp, ap);

    gemm_nt_kernel<<<gg, 256>>>(ap, Wp, bp, out, M, N, K, 0);
}

// round 3
// speedup vs baseline: 5.1868x; 5.1868x over previous
#include <cuda_runtime.h>
#include <cstdint>

#define BATCH 2
#define SEQ   4096
#define DMODEL 512
#define NHEAD 8
#define HDIM  64
#define FULLM 0xffffffffu

// Scratch (allocation-free rule: __device__ globals)
__device__ float g_q[BATCH * NHEAD * SEQ * HDIM];
__device__ float g_k[BATCH * NHEAD * SEQ * HDIM];
__device__ float g_v[BATCH * NHEAD * SEQ * HDIM];
__device__ float g_attn[BATCH * SEQ * DMODEL];

__device__ __forceinline__ unsigned f2tf(float f) {
    unsigned u;
    asm("cvt.rna.tf32.f32 %0, %1;" : "=r"(u) : "f"(f));
    return u;
}

__device__ __forceinline__ void mma_tf32(
    float& d0, float& d1, float& d2, float& d3,
    unsigned a0, unsigned a1, unsigned a2, unsigned a3,
    unsigned b0, unsigned b1)
{
    asm volatile(
        "mma.sync.aligned.m16n8k8.row.col.f32.tf32.tf32.f32 "
        "{%0,%1,%2,%3}, {%4,%5,%6,%7}, {%8,%9}, {%0,%1,%2,%3};"
        : "+f"(d0), "+f"(d1), "+f"(d2), "+f"(d3)
        : "r"(a0), "r"(a1), "r"(a2), "r"(a3), "r"(b0), "r"(b1));
}

// ---------------------------------------------------------------------------
// tf32 NT GEMM: C[m,e] = sum_k A[m,k] * W[e,k] (+bias). M rows, N=K=512.
// mode 0: C row-major [M,512] (+bias); mode 1: scatter to [B,H,S,DH].
// Block tile 128x64, BK=32, 256 threads = 8 warps of 32x32.
// ---------------------------------------------------------------------------
__global__ __launch_bounds__(256, 2)
void gemm_tf32_kernel(const float* __restrict__ A, const float* __restrict__ W,
                      const float* __restrict__ bias, float* __restrict__ C,
                      int mode)
{
    __shared__ float As[128][36];
    __shared__ float Bs[64][36];

    const int bm = blockIdx.x * 128;
    const int bn = blockIdx.y * 64;
    const int tid = threadIdx.x;
    const int lane = tid & 31;
    const int warp = tid >> 5;
    const int gr = lane >> 2;
    const int gc = lane & 3;
    const int wm = (warp >> 1) * 32;
    const int wn = (warp & 1) * 32;

    float c[2][4][4] = {};

    for (int k0 = 0; k0 < 512; k0 += 32) {
        #pragma unroll
        for (int i = 0; i < 4; i++) {
            int idx = tid + i * 256;
            int r = idx >> 3, c4 = (idx & 7) * 4;
            float4 v = *(const float4*)(A + (size_t)(bm + r) * 512 + k0 + c4);
            float4 o;
            o.x = __uint_as_float(f2tf(v.x)); o.y = __uint_as_float(f2tf(v.y));
            o.z = __uint_as_float(f2tf(v.z)); o.w = __uint_as_float(f2tf(v.w));
            *(float4*)&As[r][c4] = o;
        }
        #pragma unroll
        for (int i = 0; i < 2; i++) {
            int idx = tid + i * 256;
            int r = idx >> 3, c4 = (idx & 7) * 4;
            float4 v = *(const float4*)(W + (size_t)(bn + r) * 512 + k0 + c4);
            float4 o;
            o.x = __uint_as_float(f2tf(v.x)); o.y = __uint_as_float(f2tf(v.y));
            o.z = __uint_as_float(f2tf(v.z)); o.w = __uint_as_float(f2tf(v.w));
            *(float4*)&Bs[r][c4] = o;
        }
        __syncthreads();

        #pragma unroll
        for (int kk = 0; kk < 4; kk++) {
            const int kc = kk * 8 + gc;
            unsigned a[2][4], b[4][2];
            #pragma unroll
            for (int mt = 0; mt < 2; mt++) {
                int r = wm + mt * 16 + gr;
                a[mt][0] = __float_as_uint(As[r][kc]);
                a[mt][1] = __float_as_uint(As[r + 8][kc]);
                a[mt][2] = __float_as_uint(As[r][kc + 4]);
                a[mt][3] = __float_as_uint(As[r + 8][kc + 4]);
            }
            #pragma unroll
            for (int nt = 0; nt < 4; nt++) {
                int r = wn + nt * 8 + gr;
                b[nt][0] = __float_as_uint(Bs[r][kc]);
                b[nt][1] = __float_as_uint(Bs[r][kc + 4]);
            }
            #pragma unroll
            for (int mt = 0; mt < 2; mt++)
                #pragma unroll
                for (int nt = 0; nt < 4; nt++)
                    mma_tf32(c[mt][nt][0], c[mt][nt][1], c[mt][nt][2], c[mt][nt][3],
                             a[mt][0], a[mt][1], a[mt][2], a[mt][3],
                             b[nt][0], b[nt][1]);
        }
        __syncthreads();
    }

    #pragma unroll
    for (int mt = 0; mt < 2; mt++) {
        #pragma unroll
        for (int nt = 0; nt < 4; nt++) {
            const int r0 = bm + wm + mt * 16 + gr;
            const int e0 = bn + wn + nt * 8 + 2 * gc;
            float v0 = c[mt][nt][0], v1 = c[mt][nt][1];
            float v2 = c[mt][nt][2], v3 = c[mt][nt][3];
            if (mode == 0) {
                const float b0 = bias[e0], b1 = bias[e0 + 1];
                *(float2*)&C[(size_t)r0 * 512 + e0]        = make_float2(v0 + b0, v1 + b1);
                *(float2*)&C[(size_t)(r0 + 8) * 512 + e0]  = make_float2(v2 + b0, v3 + b1);
            } else {
                const int hh = e0 >> 6, dd = e0 & 63;
                const int bb0 = r0 / SEQ, ss0 = r0 % SEQ;
                const int bb1 = (r0 + 8) / SEQ, ss1 = (r0 + 8) % SEQ;
                *(float2*)&C[(((size_t)bb0 * NHEAD + hh) * SEQ + ss0) * HDIM + dd] =
                    make_float2(v0, v1);
                *(float2*)&C[(((size_t)bb1 * NHEAD + hh) * SEQ + ss1) * HDIM + dd] =
                    make_float2(v2, v3);
            }
        }
    }
}

// ---------------------------------------------------------------------------
// Flash attention, tf32 tensor cores. 128 q-rows/block, 8 warps (16 rows each),
// 64-key tiles in padded smem. Online softmax in fp32.
// ---------------------------------------------------------------------------
__global__ __launch_bounds__(256, 1)
void attn_tc_kernel(const float* __restrict__ Q, const float* __restrict__ Km,
                    const float* __restrict__ V, float* __restrict__ O)
{
    __shared__ float Ks[64][68];   // pad 68: QK B-frag banks (4*gr+gc) distinct
    __shared__ float Vs[64][72];   // pad 72: PV B-frag banks (8*gc+gr) distinct

    const int bh = blockIdx.y;
    const int NT = SEQ / 128;
    const int xt = blockIdx.x;
    const int qtile = (xt & 1) ? (NT - 1 - (xt >> 1)) : (xt >> 1);
    const int qb = qtile * 128;

    const int tid = threadIdx.x;
    const int lane = tid & 31;
    const int warp = tid >> 5;
    const int gr = lane >> 2;
    const int gc = lane & 3;
    const int qrow0 = qb + warp * 16 + gr;   // rows qrow0 and qrow0+8

    const float* Qb = Q  + (size_t)bh * SEQ * HDIM;
    const float* Kb = Km + (size_t)bh * SEQ * HDIM;
    const float* Vb = V  + (size_t)bh * SEQ * HDIM;

    // Q fragments, pre-scaled by 1/sqrt(64)=0.125 (exact power of 2)
    unsigned qf[8][4];
    #pragma unroll
    for (int kc = 0; kc < 8; kc++) {
        qf[kc][0] = f2tf(Qb[(size_t)qrow0 * 64 + kc * 8 + gc] * 0.125f);
        qf[kc][1] = f2tf(Qb[(size_t)(qrow0 + 8) * 64 + kc * 8 + gc] * 0.125f);
        qf[kc][2] = f2tf(Qb[(size_t)qrow0 * 64 + kc * 8 + gc + 4] * 0.125f);
        qf[kc][3] = f2tf(Qb[(size_t)(qrow0 + 8) * 64 + kc * 8 + gc + 4] * 0.125f);
    }

    float o[8][4];
    #pragma unroll
    for (int dt = 0; dt < 8; dt++)
        #pragma unroll
        for (int j = 0; j < 4; j++) o[dt][j] = 0.f;
    float m0 = -1e30f, m1 = -1e30f, l0 = 0.f, l1 = 0.f;

    const int ntiles = (qb + 128) / 64;

    for (int kt = 0; kt < ntiles; kt++) {
        // stage K/V tile (64x64), tf32-rounded
        #pragma unroll
        for (int i = 0; i < 4; i++) {
            int idx = tid + i * 256;
            int r = idx >> 4, c4 = (idx & 15) * 4;
            float4 kv = *(const float4*)(Kb + (size_t)(kt * 64 + r) * 64 + c4);
            float4 vv = *(const float4*)(Vb + (size_t)(kt * 64 + r) * 64 + c4);
            float4 ko, vo;
            ko.x = __uint_as_float(f2tf(kv.x)); ko.y = __uint_as_float(f2tf(kv.y));
            ko.z = __uint_as_float(f2tf(kv.z)); ko.w = __uint_as_float(f2tf(kv.w));
            vo.x = __uint_as_float(f2tf(vv.x)); vo.y = __uint_as_float(f2tf(vv.y));
            vo.z = __uint_as_float(f2tf(vv.z)); vo.w = __uint_as_float(f2tf(vv.w));
            *(float4*)&Ks[r][c4] = ko;
            *(float4*)&Vs[r][c4] = vo;
        }
        __syncthreads();

        // S = Q K^T  (scores, pre-scaled via Q)
        float s[8][4];
        #pragma unroll
        for (int nt = 0; nt < 8; nt++)
            #pragma unroll
            for (int j = 0; j < 4; j++) s[nt][j] = 0.f;

        #pragma unroll
        for (int kc = 0; kc < 8; kc++) {
            const int kcol = kc * 8 + gc;
            #pragma unroll
            for (int nt = 0; nt < 8; nt++) {
                unsigned b0 = __float_as_uint(Ks[nt * 8 + gr][kcol]);
                unsigned b1 = __float_as_uint(Ks[nt * 8 + gr][kcol + 4]);
                mma_tf32(s[nt][0], s[nt][1], s[nt][2], s[nt][3],
                         qf[kc][0], qf[kc][1], qf[kc][2], qf[kc][3], b0, b1);
            }
        }

        // causal mask (only last two key tiles can cross the diagonal)
        if (kt >= ntiles - 2) {
            #pragma unroll
            for (int nt = 0; nt < 8; nt++) {
                const int col = kt * 64 + nt * 8 + 2 * gc;
                if (col > qrow0)          s[nt][0] = -1e30f;
                if (col + 1 > qrow0)      s[nt][1] = -1e30f;
                if (col > qrow0 + 8)      s[nt][2] = -1e30f;
                if (col + 1 > qrow0 + 8)  s[nt][3] = -1e30f;
            }
        }

        // online softmax
        float tm0 = -1e30f, tm1 = -1e30f;
        #pragma unroll
        for (int nt = 0; nt < 8; nt++) {
            tm0 = fmaxf(tm0, fmaxf(s[nt][0], s[nt][1]));
            tm1 = fmaxf(tm1, fmaxf(s[nt][2], s[nt][3]));
        }
        tm0 = fmaxf(tm0, __shfl_xor_sync(FULLM, tm0, 1, 4));
        tm0 = fmaxf(tm0, __shfl_xor_sync(FULLM, tm0, 2, 4));
        tm1 = fmaxf(tm1, __shfl_xor_sync(FULLM, tm1, 1, 4));
        tm1 = fmaxf(tm1, __shfl_xor_sync(FULLM, tm1, 2, 4));

        const float nm0 = fmaxf(m0, tm0);
        const float nm1 = fmaxf(m1, tm1);
        const float sc0 = __expf(m0 - nm0);
        const float sc1 = __expf(m1 - nm1);

        float r0 = 0.f, r1 = 0.f;
        #pragma unroll
        for (int nt = 0; nt < 8; nt++) {
            s[nt][0] = __expf(s[nt][0] - nm0);
            s[nt][1] = __expf(s[nt][1] - nm0);
            s[nt][2] = __expf(s[nt][2] - nm1);
            s[nt][3] = __expf(s[nt][3] - nm1);
            r0 += s[nt][0] + s[nt][1];
            r1 += s[nt][2] + s[nt][3];
        }
        r0 += __shfl_xor_sync(FULLM, r0, 1, 4);
        r0 += __shfl_xor_sync(FULLM, r0, 2, 4);
        r1 += __shfl_xor_sync(FULLM, r1, 1, 4);
        r1 += __shfl_xor_sync(FULLM, r1, 2, 4);
        l0 = l0 * sc0 + r0;
        l1 = l1 * sc1 + r1;

        #pragma unroll
        for (int dt = 0; dt < 8; dt++) {
            o[dt][0] *= sc0; o[dt][1] *= sc0;
            o[dt][2] *= sc1; o[dt][3] *= sc1;
        }

        // O += P V : build A-frags from P accum layout via quad shuffles
        const int srcA = gc >> 1;
        const int srcB = srcA + 2;
        const bool odd = (gc & 1);
        #pragma unroll
        for (int kc = 0; kc < 8; kc++) {
            float t0 = __shfl_sync(FULLM, s[kc][0], srcA, 4);
            float t1 = __shfl_sync(FULLM, s[kc][1], srcA, 4);
            float t2 = __shfl_sync(FULLM, s[kc][2], srcA, 4);
            float t3 = __shfl_sync(FULLM, s[kc][3], srcA, 4);
            float u0 = __shfl_sync(FULLM, s[kc][0], srcB, 4);
            float u1 = __shfl_sync(FULLM, s[kc][1], srcB, 4);
            float u2 = __shfl_sync(FULLM, s[kc][2], srcB, 4);
            float u3 = __shfl_sync(FULLM, s[kc][3], srcB, 4);
            unsigned a0 = f2tf(odd ? t1 : t0);
            unsigned a1 = f2tf(odd ? t3 : t2);
            unsigned a2 = f2tf(odd ? u1 : u0);
            unsigned a3 = f2tf(odd ? u3 : u2);
            const int krow = kc * 8 + gc;
            #pragma unroll
            for (int dt = 0; dt < 8; dt++) {
                unsigned b0 = __float_as_uint(Vs[krow][dt * 8 + gr]);
                unsigned b1 = __float_as_uint(Vs[krow + 4][dt * 8 + gr]);
                mma_tf32(o[dt][0], o[dt][1], o[dt][2], o[dt][3],
                         a0, a1, a2, a3, b0, b1);
            }
        }

        m0 = nm0; m1 = nm1;
        __syncthreads();
    }

    // epilogue: normalize and store to [B, S, H, DH]
    const float inv0 = 1.f / l0;
    const float inv1 = 1.f / l1;
    const int b = bh >> 3, h = bh & 7;
    #pragma unroll
    for (int dt = 0; dt < 8; dt++) {
        const int col = dt * 8 + 2 * gc;
        *(float2*)&O[(((size_t)b * SEQ + qrow0) * NHEAD + h) * HDIM + col] =
            make_float2(o[dt][0] * inv0, o[dt][1] * inv0);
        *(float2*)&O[(((size_t)b * SEQ + qrow0 + 8) * NHEAD + h) * HDIM + col] =
            make_float2(o[dt][2] * inv1, o[dt][3] * inv1);
    }
}

// ---------------------------------------------------------------------------
extern "C" void kernel_launch(void* const* d_in, const int* in_sizes, int n_in,
                              void* d_out, int out_size)
{
    const float* x  = (const float*)d_in[0];
    const float* Wq = (const float*)d_in[1];
    const float* Wk = (const float*)d_in[2];
    const float* Wv = (const float*)d_in[3];
    const float* Wp = (const float*)d_in[4];
    const float* bp = (const float*)d_in[5];
    float* out = (float*)d_out;

    float *qp, *kp, *vp, *ap;
    cudaGetSymbolAddress((void**)&qp, g_q);
    cudaGetSymbolAddress((void**)&kp, g_k);
    cudaGetSymbolAddress((void**)&vp, g_v);
    cudaGetSymbolAddress((void**)&ap, g_attn);

    dim3 gg(BATCH * SEQ / 128, DMODEL / 64);   // (64, 8)
    gemm_tf32_kernel<<<gg, 256>>>(x, Wq, nullptr, qp, 1);
    gemm_tf32_kernel<<<gg, 256>>>(x, Wk, nullptr, kp, 1);
    gemm_tf32_kernel<<<gg, 256>>>(x, Wv, nullptr, vp, 1);

    dim3 ga(SEQ / 128, BATCH * NHEAD);          // (32, 16)
    attn_tc_kernel<<<ga, 256>>>(qp, kp, vp, ap);

    gemm_tf32_kernel<<<gg, 256>>>(ap, Wp, bp, out, 0);
}